// round 15
// baseline (speedup 1.0000x reference)
#include <cuda_runtime.h>
#include <math.h>

// Problem constants (B=2, C=48, 32^3 volume)
#define BB   2
#define CC   48
#define SS   (32*32*32)          // 32768
#define OFFC 81

typedef unsigned long long ull;
typedef unsigned int uint32;

// ---------------- f32x2 packed helpers (sm_100+) ----------------
__device__ __forceinline__ ull pack2(float a, float b) {
    ull r;
    asm("mov.b64 %0, {%1, %2};" : "=l"(r) : "f"(a), "f"(b));
    return r;
}
__device__ __forceinline__ void fma2(ull& d, ull a, ull b) {
    asm("fma.rn.f32x2 %0, %1, %2, %0;" : "+l"(d) : "l"(a), "l"(b));
}
__device__ __forceinline__ void unpack2(float& lo, float& hi, ull v) {
    asm("mov.b64 {%0, %1}, %2;" : "=f"(lo), "=f"(hi) : "l"(v));
}

// ---------------- tf32 helpers ----------------
__device__ __forceinline__ float to_tf32(float v) {
    uint32 b;
    asm("cvt.rna.tf32.f32 %0, %1;" : "=r"(b) : "f"(v));
    return __uint_as_float(b);
}
// D += A*B  (m16n8k8, A row-major, B col-major, tf32 in, f32 acc)
__device__ __forceinline__ void mma8(float* d,
                                     float a0, float a1, float a2, float a3,
                                     float b0, float b1) {
    asm volatile(
        "mma.sync.aligned.m16n8k8.row.col.f32.tf32.tf32.f32 "
        "{%0,%1,%2,%3}, {%4,%5,%6,%7}, {%8,%9}, {%0,%1,%2,%3};"
        : "+f"(d[0]), "+f"(d[1]), "+f"(d[2]), "+f"(d[3])
        : "r"(__float_as_uint(a0)), "r"(__float_as_uint(a1)),
          "r"(__float_as_uint(a2)), "r"(__float_as_uint(a3)),
          "r"(__float_as_uint(b0)), "r"(__float_as_uint(b1)));
}

// ---------------- scratch (device globals; allocation-free) ----------------
__device__ float g_xn  [BB*CC*SS];   // 0
__device__ float g_u   [BB*CC*SS];   // 1
__device__ float g_a1  [BB*CC*SS];   // 2
__device__ float g_a2  [BB*CC*SS];   // 3
__device__ float g_off [BB*OFFC*SS]; // 4
__device__ float g_a3  [BB*CC*SS];   // 5  (deform partial 0)
__device__ float g_skip[BB*CC*SS];   // 6
__device__ float g_h1  [BB*CC*SS];   // 7  (deform partial 1, later u1 out)
__device__ float g_attn[BB*CC*SS];   // 8  (deform partial 2, later u2 out)
__device__ float g_dcwt[27*CC*CC];   // dc_w transposed to [tap][c][o]

// Pre-split conv weights for tensor-core path: hi plane then lo plane.
// Row layout: [c*32 + krow][ocol], krow = kchunk*8+kk; cols = Npad (<=96).
#define WMMA_HALF (CC*32*96)
__device__ float g_wmma[2 * WMMA_HALF];

__device__ __forceinline__ float* bufsel(int id, const float* ext) {
    switch (id) {
        case 0: return g_xn;   case 1: return g_u;    case 2: return g_a1;
        case 3: return g_a2;   case 4: return g_off;  case 5: return g_a3;
        case 6: return g_skip; case 7: return g_h1;   case 8: return g_attn;
    }
    return (float*)ext;
}

// ---------------- fused LayerNorm + proj_1 + GELU ----------------
__global__ void __launch_bounds__(256) k_lnpw(
    const float* __restrict__ x,
    const float* __restrict__ ls, const float* __restrict__ lb,
    const float* __restrict__ w,  const float* __restrict__ bias)
{
    __shared__ __align__(16) float ws2[CC * CC];   // [c][o], o contiguous
    __shared__ float bs[CC];
    for (int i = threadIdx.x; i < CC * CC; i += blockDim.x) {
        int o = i / CC, c = i - o * CC;
        ws2[c * CC + o] = w[i];
    }
    if (threadIdx.x < CC) bs[threadIdx.x] = bias[threadIdx.x];
    __syncthreads();

    int i = blockIdx.x * blockDim.x + threadIdx.x;
    int b = i >> 15, s = i & (SS - 1);
    const float* xb = x + (size_t)b * CC * SS + s;

    float s1 = 0.f, s2 = 0.f;
    #pragma unroll 8
    for (int c = 0; c < CC; c++) { float v = xb[c * SS]; s1 += v; s2 += v * v; }
    float mu  = s1 * (1.f / CC);
    float var = s2 * (1.f / CC) - mu * mu;
    float inv = rsqrtf(var + 1e-5f);

    float* xnp = g_xn + (size_t)b * CC * SS + s;

    ull acc2[CC / 2];
    #pragma unroll
    for (int q = 0; q < CC / 2; q++) acc2[q] = 0ull;

    const ulonglong2* wrow = (const ulonglong2*)ws2;
    #pragma unroll 4
    for (int c = 0; c < CC; c++) {
        float v = (xb[c * SS] - mu) * inv * ls[c] + lb[c];
        xnp[c * SS] = v;
        ull vv = pack2(v, v);
        #pragma unroll
        for (int q = 0; q < CC / 4; q++) {
            ulonglong2 wq = wrow[c * (CC / 4) + q];
            fma2(acc2[2 * q + 0], wq.x, vv);
            fma2(acc2[2 * q + 1], wq.y, vv);
        }
    }

    float* up = g_u + (size_t)b * CC * SS + s;
    #pragma unroll
    for (int q = 0; q < CC / 2; q++) {
        float a0, a1;
        unpack2(a0, a1, acc2[q]);
        float v0 = a0 + bs[2 * q + 0];
        float v1 = a1 + bs[2 * q + 1];
        up[(2 * q + 0) * SS] = 0.5f * v0 * (1.f + erff(v0 * 0.70710678118654752f));
        up[(2 * q + 1) * SS] = 0.5f * v1 * (1.f + erff(v1 * 0.70710678118654752f));
    }
}

// ---------------- 1x1x1 pointwise 48x48, f32x2 output pairs ----------------
// mode 1: out = aux1 * (acc + bias[o]); input = a3+h1+attn partials + dcb[c]
// mode 2: out = aux1 + gamma[o]*(acc + bias[o] + g_xn)
// mode 3: out = aux1 + acc + bias[o]
__global__ void __launch_bounds__(256) k_pw48(
    int in_id, const float* __restrict__ ext_in,
    const float* __restrict__ w, const float* __restrict__ bias,
    int a1_id, const float* __restrict__ ext_a1,
    const float* __restrict__ gamma,
    const float* __restrict__ dcb,
    int out_id, float* __restrict__ ext_out,
    int mode)
{
    __shared__ __align__(16) float ws2[CC * CC];   // [c][o], o contiguous
    __shared__ float bs[CC];
    __shared__ float dcs[CC];
    for (int i = threadIdx.x; i < CC * CC; i += blockDim.x) {
        int o = i / CC, c = i - o * CC;
        ws2[c * CC + o] = w[i];
    }
    if (threadIdx.x < CC) {
        bs[threadIdx.x] = bias[threadIdx.x];
        dcs[threadIdx.x] = (dcb != nullptr) ? dcb[threadIdx.x] : 0.f;
    }
    __syncthreads();

    int i = blockIdx.x * blockDim.x + threadIdx.x;
    int b = i >> 15, s = i & (SS - 1);
    size_t base = (size_t)b * CC * SS + s;
    const float* in = bufsel(in_id, ext_in) + base;
    const float* pp1 = g_h1 + base;    // deform partial 1 (mode 1 only)
    const float* pp2 = g_attn + base;  // deform partial 2 (mode 1 only)

    ull acc2[CC / 2];
    #pragma unroll
    for (int q = 0; q < CC / 2; q++) acc2[q] = 0ull;

    const ulonglong2* wrow = (const ulonglong2*)ws2;
    if (mode == 1) {
        #pragma unroll 4
        for (int c = 0; c < CC; c++) {
            float v = in[c * SS] + pp1[c * SS] + pp2[c * SS] + dcs[c];
            ull vv = pack2(v, v);
            #pragma unroll
            for (int q = 0; q < CC / 4; q++) {
                ulonglong2 wq = wrow[c * (CC / 4) + q];
                fma2(acc2[2 * q + 0], wq.x, vv);
                fma2(acc2[2 * q + 1], wq.y, vv);
            }
        }
    } else {
        #pragma unroll 4
        for (int c = 0; c < CC; c++) {
            float v = in[c * SS];
            ull vv = pack2(v, v);
            #pragma unroll
            for (int q = 0; q < CC / 4; q++) {
                ulonglong2 wq = wrow[c * (CC / 4) + q];
                fma2(acc2[2 * q + 0], wq.x, vv);
                fma2(acc2[2 * q + 1], wq.y, vv);
            }
        }
    }

    float acc[CC];
    #pragma unroll
    for (int q = 0; q < CC / 2; q++) unpack2(acc[2 * q], acc[2 * q + 1], acc2[q]);

    float* outp = bufsel(out_id, (const float*)ext_out) + base;
    const float* a1p = bufsel(a1_id, ext_a1) + base;
    const float* a2p = g_xn + base;

    if (mode == 1) {
        #pragma unroll
        for (int o = 0; o < CC; o++)
            outp[o * SS] = a1p[o * SS] * (acc[o] + bs[o]);
    } else if (mode == 2) {
        #pragma unroll
        for (int o = 0; o < CC; o++)
            outp[o * SS] = a1p[o * SS] + gamma[o] * (acc[o] + bs[o] + a2p[o * SS]);
    } else {
        #pragma unroll
        for (int o = 0; o < CC; o++)
            outp[o * SS] = a1p[o * SS] + acc[o] + bs[o];
    }
}

// ---------------- depthwise KxKxK: 4 x-adjacent outputs/thread, float4 rows ----------------
template<int K, int PAD, int DIL>
__global__ void __launch_bounds__(256) k_dw(int in_id, const float* __restrict__ w,
                                            const float* __restrict__ bias, int out_id) {
    constexpr int LOW = -(((PAD) + 3) / 4) * 4;
    constexpr int HI  = 3 + (K - 1) * DIL - PAD;
    constexpr int NCH = (HI - LOW) / 4 + 1;
    __shared__ float ws[K * K * K];
    int c = blockIdx.y, b = blockIdx.z;
    for (int i = threadIdx.x; i < K * K * K; i += blockDim.x)
        ws[i] = w[c * K * K * K + i];
    __syncthreads();
    int s = blockIdx.x * 1024 + threadIdx.x * 4;
    int z = s >> 10, y = (s >> 5) & 31, x0 = s & 31;
    const float* ib = bufsel(in_id, nullptr) + ((size_t)b * CC + c) * SS;

    float b0 = bias[c];
    float acc[4] = {b0, b0, b0, b0};

    #pragma unroll
    for (int i = 0; i < K; i++) {
        int zz = z + i * DIL - PAD;
        if ((unsigned)zz >= 32u) continue;
        #pragma unroll
        for (int j = 0; j < K; j++) {
            int yy = y + j * DIL - PAD;
            if ((unsigned)yy >= 32u) continue;
            const float* row = ib + (zz << 10) + (yy << 5);
            float v[NCH * 4];
            #pragma unroll
            for (int ch = 0; ch < NCH; ch++) {
                int xb = x0 + LOW + ch * 4;
                if (xb >= 0 && xb <= 28) {
                    float4 t = *(const float4*)(row + xb);
                    v[ch * 4 + 0] = t.x; v[ch * 4 + 1] = t.y;
                    v[ch * 4 + 2] = t.z; v[ch * 4 + 3] = t.w;
                } else {
                    v[ch * 4 + 0] = 0.f; v[ch * 4 + 1] = 0.f;
                    v[ch * 4 + 2] = 0.f; v[ch * 4 + 3] = 0.f;
                }
            }
            const float* wr = ws + (i * K + j) * K;
            #pragma unroll
            for (int l = 0; l < K; l++) {
                float wv = wr[l];
                #pragma unroll
                for (int u = 0; u < 4; u++)
                    acc[u] += wv * v[u + l * DIL - PAD - LOW];
            }
        }
    }
    float* op = bufsel(out_id, nullptr) + ((size_t)b * CC + c) * SS + s;
    *(float4*)op = make_float4(acc[0], acc[1], acc[2], acc[3]);
}

// ---------------- conv weight prepack for MMA: hi/lo tf32 split ----------------
// dst[(c*32 + krow)*Npad + o] = w[o][c][tap=krow], zero for pad tap/o.
__global__ void k_wprep(const float* __restrict__ w, int O, int Npad) {
    int i = blockIdx.x * blockDim.x + threadIdx.x;
    int total = CC * 32 * Npad;
    if (i >= total) return;
    int o  = i % Npad;
    int r  = i / Npad;
    int t  = r & 31;       // krow = tap index (0..31, taps 27..31 zero)
    int c  = r >> 5;
    float v = (o < O && t < 27) ? w[(size_t)o * (CC * 27) + c * 27 + t] : 0.f;
    float hi = to_tf32(v);
    g_wmma[i] = hi;
    g_wmma[WMMA_HALF + i] = to_tf32(v - hi);
}

// ---------------- dense 3x3x3 conv via tf32x3 MMA, B staged in smem ----------------
// Block: 128 contiguous voxels (4 x-rows), 8 warps x 16 voxels. Channel slab = 2.
// sA: halo tile hi/lo (9.8 KB). sB: weights hi/lo for slab, stride NO+8 so the
// 4-row x 8-col fragment LDS pattern is bank-conflict-free.
// mode 0: +bias; 1: leaky(bn); 2: leaky(bn + skip)
template<int NO>
__global__ void __launch_bounds__(256) k_c3mma(
    int in_id, const float* __restrict__ bias,
    const float* __restrict__ bs2, const float* __restrict__ bbp,
    const float* __restrict__ bm, const float* __restrict__ bv,
    int skip_id, int out_id, int O, int Npad, int mode)
{
    constexpr int NC   = NO / 8;
    constexpr int BSTR = NO + 8;
    constexpr int TP   = 3 * 6 * 34;   // 612 floats per channel halo tile
    __shared__ float sA[2][2][TP];           // [hi/lo][cL][pos]
    __shared__ float sB[2][2][32][BSTR];     // [hi/lo][cL][krow][o]

    const int b      = blockIdx.z;
    const int n0base = blockIdx.y * NO;
    const int s0     = blockIdx.x * 128;
    const int z  = s0 >> 10;
    const int y0 = (s0 >> 5) & 31;
    const float* ib = bufsel(in_id, nullptr) + (size_t)b * CC * SS;

    const int lane = threadIdx.x & 31;
    const int warp = threadIdx.x >> 5;
    const int gid  = lane >> 2;    // 0..7
    const int tig  = lane & 3;     // 0..3

    // A-fragment row positions in padded tile (voxels m and m+8 of this warp's 16)
    const int mA = warp * 16 + gid;
    const int mB = mA + 8;
    const int posA = (7 + (mA >> 5)) * 34 + (mA & 31) + 1;
    const int posB = (7 + (mB >> 5)) * 34 + (mB & 31) + 1;

    // tap offsets for this thread's K columns (taps tig+8kc and tig+4+8kc)
    int offA[4], offB[4];
    #pragma unroll
    for (int kc = 0; kc < 4; kc++) {
        int tA = kc * 8 + tig, tB = tA + 4;
        offA[kc] = (tA < 27) ? (tA / 9 - 1) * 204 + ((tA % 9) / 3 - 1) * 34 + (tA % 3 - 1) : 0;
        offB[kc] = (tB < 27) ? (tB / 9 - 1) * 204 + ((tB % 9) / 3 - 1) * 34 + (tB % 3 - 1) : 0;
    }

    float acc[NC][4];
    #pragma unroll
    for (int n = 0; n < NC; n++) {
        acc[n][0] = 0.f; acc[n][1] = 0.f; acc[n][2] = 0.f; acc[n][3] = 0.f;
    }

    for (int cb = 0; cb < CC; cb += 2) {
        __syncthreads();
        // stage A: 2 channels of halo tile, hi/lo split
        for (int i = threadIdx.x; i < 2 * TP; i += 256) {
            int cL = i / TP, p = i - cL * TP;
            int zi = p / 204; int r = p - zi * 204;
            int yi = r / 34;  int xi = r - yi * 34;
            int zz = z + zi - 1, yy = y0 + yi - 1, xx = xi - 1;
            float v = 0.f;
            if ((unsigned)zz < 32u && (unsigned)yy < 32u && (unsigned)xx < 32u)
                v = ib[(size_t)(cb + cL) * SS + (zz << 10) + (yy << 5) + xx];
            float hv = to_tf32(v);
            sA[0][cL][p] = hv;
            sA[1][cL][p] = to_tf32(v - hv);
        }
        // stage B: 2 channels x 32 krows x NO cols, both planes
        for (int i = threadIdx.x; i < 2 * 32 * NO; i += 256) {
            int cL = i / (32 * NO);
            int r  = i - cL * (32 * NO);
            int kr = r / NO;
            int o  = r - kr * NO;
            size_t gidx = (size_t)((cb + cL) * 32 + kr) * Npad + n0base + o;
            sB[0][cL][kr][o] = g_wmma[gidx];
            sB[1][cL][kr][o] = g_wmma[WMMA_HALF + gidx];
        }
        __syncthreads();

        #pragma unroll
        for (int cL = 0; cL < 2; cL++) {
            const float* Ah = sA[0][cL];
            const float* Al = sA[1][cL];
            #pragma unroll
            for (int kc = 0; kc < 4; kc++) {
                float ah0 = Ah[posA + offA[kc]];
                float ah1 = Ah[posB + offA[kc]];
                float ah2 = Ah[posA + offB[kc]];
                float ah3 = Ah[posB + offB[kc]];
                float al0 = Al[posA + offA[kc]];
                float al1 = Al[posB + offA[kc]];
                float al2 = Al[posA + offB[kc]];
                float al3 = Al[posB + offB[kc]];
                #pragma unroll
                for (int n = 0; n < NC; n++) {
                    int o = n * 8 + gid;
                    float bh0 = sB[0][cL][kc * 8 + tig][o];
                    float bh1 = sB[0][cL][kc * 8 + tig + 4][o];
                    float bl0 = sB[1][cL][kc * 8 + tig][o];
                    float bl1 = sB[1][cL][kc * 8 + tig + 4][o];
                    mma8(acc[n], ah0, ah1, ah2, ah3, bh0, bh1);   // hi*hi
                    mma8(acc[n], ah0, ah1, ah2, ah3, bl0, bl1);   // hi*lo
                    mma8(acc[n], al0, al1, al2, al3, bh0, bh1);   // lo*hi
                }
            }
        }
    }

    // epilogue: c0=(m=gid, o=tig*2), c1=(gid, tig*2+1), c2=(gid+8, tig*2), c3=(gid+8, tig*2+1)
    float* outb = bufsel(out_id, nullptr) + (size_t)b * O * SS + s0 + warp * 16 + gid;
    const float* skp = (mode == 2)
        ? bufsel(skip_id, nullptr) + (size_t)b * O * SS + s0 + warp * 16 + gid : nullptr;

    #pragma unroll
    for (int n = 0; n < NC; n++) {
        int oa = n0base + n * 8 + tig * 2;
        int ob = oa + 1;
        if (mode == 0) {
            if (oa < O) {
                float bb = bias[oa];
                outb[(size_t)oa * SS]     = acc[n][0] + bb;
                outb[(size_t)oa * SS + 8] = acc[n][2] + bb;
            }
            if (ob < O) {
                float bb = bias[ob];
                outb[(size_t)ob * SS]     = acc[n][1] + bb;
                outb[(size_t)ob * SS + 8] = acc[n][3] + bb;
            }
        } else {
            {
                float sc = bs2[oa] * rsqrtf(bv[oa] + 1e-5f);
                float sh = bbp[oa] - bm[oa] * sc;
                float h0 = acc[n][0] * sc + sh;
                float h2 = acc[n][2] * sc + sh;
                if (mode == 2) { h0 += skp[(size_t)oa * SS]; h2 += skp[(size_t)oa * SS + 8]; }
                outb[(size_t)oa * SS]     = (h0 >= 0.f) ? h0 : 0.01f * h0;
                outb[(size_t)oa * SS + 8] = (h2 >= 0.f) ? h2 : 0.01f * h2;
            }
            {
                float sc = bs2[ob] * rsqrtf(bv[ob] + 1e-5f);
                float sh = bbp[ob] - bm[ob] * sc;
                float h1 = acc[n][1] * sc + sh;
                float h3 = acc[n][3] * sc + sh;
                if (mode == 2) { h1 += skp[(size_t)ob * SS]; h3 += skp[(size_t)ob * SS + 8]; }
                outb[(size_t)ob * SS]     = (h1 >= 0.f) ? h1 : 0.01f * h1;
                outb[(size_t)ob * SS + 8] = (h3 >= 0.f) ? h3 : 0.01f * h3;
            }
        }
    }
}

// ---------------- transpose dc_w [o][c][k] -> [k][c][o] ----------------
__global__ void k_wt(const float* __restrict__ w) {
    int i = blockIdx.x * blockDim.x + threadIdx.x;
    if (i >= CC * CC * 27) return;
    int o = i / (CC * 27);
    int r = i - o * (CC * 27);
    int c = r / 27;
    int k = r - c * 27;
    g_dcwt[(k * CC + c) * CC + o] = w[i];
}

// ---------------- deformable conv: 3-way tap split, 3-tap smem staging, f32x2 ----------------
__global__ void __launch_bounds__(256, 2) k_deform() {
    __shared__ __align__(16) float wt_s[3][CC * CC];   // [tap-in-triple][c][o]
    int s = blockIdx.x * blockDim.x + threadIdx.x;
    int b = blockIdx.y;
    int g = blockIdx.z;
    int z = s >> 10, y = (s >> 5) & 31, x = s & 31;
    const float* a   = g_a2  + (size_t)b * CC * SS;
    const float* off = g_off + (size_t)b * OFFC * SS + s;

    ull acc2[CC / 2];
    #pragma unroll
    for (int q = 0; q < CC / 2; q++) acc2[q] = 0ull;

    #pragma unroll 1
    for (int kt0 = g * 9; kt0 < g * 9 + 9; kt0 += 3) {
        __syncthreads();
        {
            const float4* src = (const float4*)(g_dcwt + kt0 * CC * CC);
            float4* dst = (float4*)wt_s[0];
            for (int i = threadIdx.x; i < 3 * CC * CC / 4; i += blockDim.x)
                dst[i] = src[i];
        }
        __syncthreads();

        #pragma unroll 1
        for (int tloc = 0; tloc < 3; tloc++) {
            int kt = kt0 + tloc;
            int kd = kt / 9 - 1, kh = (kt / 3) % 3 - 1, kw = kt % 3 - 1;
            float zf = (float)(z + kd) + off[(kt * 3 + 0) * SS];
            float yf = (float)(y + kh) + off[(kt * 3 + 1) * SS];
            float xf = (float)(x + kw) + off[(kt * 3 + 2) * SS];
            float z0 = floorf(zf), y0 = floorf(yf), x0 = floorf(xf);
            float tz = zf - z0, ty = yf - y0, tx = xf - x0;
            int iz0 = (int)z0, iy0 = (int)y0, ix0 = (int)x0;

            int idx8[8];
            ull w8v[8];
            #pragma unroll
            for (int dz = 0; dz < 2; dz++)
            #pragma unroll
            for (int dy = 0; dy < 2; dy++)
            #pragma unroll
            for (int dx = 0; dx < 2; dx++) {
                int j = dz * 4 + dy * 2 + dx;
                int zi = iz0 + dz, yi = iy0 + dy, xi = ix0 + dx;
                bool valid = (zi >= 0 && zi < 32 && yi >= 0 && yi < 32 && xi >= 0 && xi < 32);
                float wg = (dz ? tz : 1.f - tz) * (dy ? ty : 1.f - ty) * (dx ? tx : 1.f - tx);
                int zc = min(max(zi, 0), 31), yc = min(max(yi, 0), 31), xc = min(max(xi, 0), 31);
                idx8[j] = (zc << 10) + (yc << 5) + xc;
                float wf = valid ? wg : 0.f;
                w8v[j] = pack2(wf, wf);
            }

            const float* wts = wt_s[tloc];
            for (int c = 0; c < CC; c += 2) {
                const float* ac0 = a + c * SS;
                const float* ac1 = ac0 + SS;
                ull valv = 0ull;
                #pragma unroll
                for (int j = 0; j < 8; j++)
                    fma2(valv, pack2(ac0[idx8[j]], ac1[idx8[j]]), w8v[j]);
                float v0, v1;
                unpack2(v0, v1, valv);
                ull vv0 = pack2(v0, v0), vv1 = pack2(v1, v1);

                const ulonglong2* w0 = (const ulonglong2*)(wts + (c + 0) * CC);
                const ulonglong2* w1 = (const ulonglong2*)(wts + (c + 1) * CC);
                #pragma unroll
                for (int q = 0; q < CC / 4; q++) {
                    ulonglong2 wa = w0[q];
                    fma2(acc2[2 * q + 0], wa.x, vv0);
                    fma2(acc2[2 * q + 1], wa.y, vv0);
                }
                #pragma unroll
                for (int q = 0; q < CC / 4; q++) {
                    ulonglong2 wb = w1[q];
                    fma2(acc2[2 * q + 0], wb.x, vv1);
                    fma2(acc2[2 * q + 1], wb.y, vv1);
                }
            }
        }
    }

    int outid = (g == 0) ? 5 : (g == 1) ? 7 : 8;
    float* ob = bufsel(outid, nullptr) + (size_t)b * CC * SS + s;
    #pragma unroll
    for (int q = 0; q < CC / 2; q++) {
        float a0, a1;
        unpack2(a0, a1, acc2[q]);
        ob[(2 * q + 0) * SS] = a0;
        ob[(2 * q + 1) * SS] = a1;
    }
}

// ---------------- launch: kernel launches ONLY ----------------
extern "C" void kernel_launch(void* const* d_in, const int* in_sizes, int n_in,
                              void* d_out, int out_size) {
    const float* x     = (const float*)d_in[0];
    const float* ln_s  = (const float*)d_in[1];
    const float* ln_b  = (const float*)d_in[2];
    const float* gamma = (const float*)d_in[3];
    const float* p1_w  = (const float*)d_in[4];
    const float* p1_b  = (const float*)d_in[5];
    const float* p2_w  = (const float*)d_in[6];
    const float* p2_b  = (const float*)d_in[7];
    const float* c0_w  = (const float*)d_in[8];
    const float* c0_b  = (const float*)d_in[9];
    const float* cs_w  = (const float*)d_in[10];
    const float* cs_b  = (const float*)d_in[11];
    const float* off_w = (const float*)d_in[12];
    const float* off_b = (const float*)d_in[13];
    const float* dc_w  = (const float*)d_in[14];
    const float* dc_b  = (const float*)d_in[15];
    const float* c1_w  = (const float*)d_in[16];
    const float* c1_b  = (const float*)d_in[17];
    const float* u1_w  = (const float*)d_in[18];
    const float* bn1_s = (const float*)d_in[19];
    const float* bn1_b = (const float*)d_in[20];
    const float* bn1_m = (const float*)d_in[21];
    const float* bn1_v = (const float*)d_in[22];
    const float* u2_w  = (const float*)d_in[23];
    const float* bn2_s = (const float*)d_in[24];
    const float* bn2_b = (const float*)d_in[25];
    const float* bn2_m = (const float*)d_in[26];
    const float* bn2_v = (const float*)d_in[27];
    const float* pr_w  = (const float*)d_in[28];
    const float* pr_b  = (const float*)d_in[29];
    float* out = (float*)d_out;

    dim3 pwGrid((BB * SS) / 256);
    dim3 dwGrid(SS / 1024, CC, BB);
    dim3 mmaOffGrid(SS / 128, 3, BB);   // NO=32 x 3 chunks covers 96 >= 81
    dim3 mmaUGrid(SS / 128, 1, BB);     // NO=48, single chunk

    // 1. fused LayerNorm + proj_1 + GELU: x -> g_xn (0), g_u (1)
    k_lnpw<<<pwGrid, 256>>>(x, ln_s, ln_b, p1_w, p1_b);
    // 2. depthwise 5x5x5 pad 2: g_u -> g_a1 (2)
    k_dw<5, 2, 1><<<dwGrid, 256>>>(1, c0_w, c0_b, 2);
    // 3. depthwise 7x7x7 dil 3 pad 9: g_a1 -> g_a2 (3)
    k_dw<7, 9, 3><<<dwGrid, 256>>>(2, cs_w, cs_b, 3);
    // 4a. prepack offset-conv weights (Npad=96), 4b. offset conv via MMA
    k_wprep<<<(CC * 32 * 96 + 255) / 256, 256>>>(off_w, OFFC, 96);
    k_c3mma<32><<<mmaOffGrid, 256>>>(3, off_b,
                                     nullptr, nullptr, nullptr, nullptr,
                                     -1, 4, OFFC, 96, 0);
    // 5. transpose deform weights
    k_wt<<<(CC * CC * 27 + 255) / 256, 256>>>(dc_w);
    // 6. deformable conv, 3 tap groups: partials -> g_a3 (5), g_h1 (7), g_attn (8)
    k_deform<<<dim3(SS / 256, BB, 3), 256>>>();
    // 7. c1 1x1x1 on (sum of partials + dc_b), gate mult with g_u -> g_a1 (2)
    k_pw48<<<pwGrid, 256>>>(5, nullptr, c1_w, c1_b, 1, nullptr, nullptr, dc_b,
                            2, nullptr, 1);
    // 8. proj_2 + shortcut + gamma residual: g_a1, aux x, g_xn -> g_skip (6)
    k_pw48<<<pwGrid, 256>>>(2, nullptr, p2_w, p2_b, -1, x, gamma, nullptr,
                            6, nullptr, 2);
    // 9a/9b. u1 conv3 + BN1 + leaky via MMA: g_skip -> g_h1 (7)
    k_wprep<<<(CC * 32 * 48 + 255) / 256, 256>>>(u1_w, CC, 48);
    k_c3mma<48><<<mmaUGrid, 256>>>(6, nullptr,
                                   bn1_s, bn1_b, bn1_m, bn1_v,
                                   -1, 7, CC, 48, 1);
    // 10a/10b. u2 conv3 + BN2 + skip + leaky via MMA: g_h1 -> g_attn (8)
    k_wprep<<<(CC * 32 * 48 + 255) / 256, 256>>>(u2_w, CC, 48);
    k_c3mma<48><<<mmaUGrid, 256>>>(7, nullptr,
                                   bn2_s, bn2_b, bn2_m, bn2_v,
                                   6, 8, CC, 48, 2);
    // 11. projconv 1x1x1 + skip -> out (external)
    k_pw48<<<pwGrid, 256>>>(8, nullptr, pr_w, pr_b, 6, nullptr, nullptr, nullptr,
                            -1, out, 3);
}

// round 16
// speedup vs baseline: 1.0495x; 1.0495x over previous
#include <cuda_runtime.h>
#include <math.h>

// Problem constants (B=2, C=48, 32^3 volume)
#define BB   2
#define CC   48
#define SS   (32*32*32)          // 32768
#define OFFC 81

typedef unsigned long long ull;

// ---------------- f32x2 packed helpers (sm_100+) ----------------
__device__ __forceinline__ ull pack2(float a, float b) {
    ull r;
    asm("mov.b64 %0, {%1, %2};" : "=l"(r) : "f"(a), "f"(b));
    return r;
}
__device__ __forceinline__ void fma2(ull& d, ull a, ull b) {
    asm("fma.rn.f32x2 %0, %1, %2, %0;" : "+l"(d) : "l"(a), "l"(b));
}
__device__ __forceinline__ void unpack2(float& lo, float& hi, ull v) {
    asm("mov.b64 {%0, %1}, %2;" : "=f"(lo), "=f"(hi) : "l"(v));
}

// ---------------- scratch (device globals; allocation-free) ----------------
__device__ float g_xn  [BB*CC*SS];   // 0
__device__ float g_u   [BB*CC*SS];   // 1
__device__ float g_a1  [BB*CC*SS];   // 2 (unused in fused path; kept for ids)
__device__ float g_a2  [BB*CC*SS];   // 3
__device__ float g_off [BB*OFFC*SS]; // 4
__device__ float g_a3  [BB*CC*SS];   // 5  (deform partial 0)
__device__ float g_skip[BB*CC*SS];   // 6
__device__ float g_h1  [BB*CC*SS];   // 7  (deform partial 1, later u1 out)
__device__ float g_attn[BB*CC*SS];   // 8  (deform partial 2, later u2 out)
__device__ float g_dcwt[27*CC*CC];   // dc_w transposed to [tap][c][o]

__device__ __forceinline__ float* bufsel(int id, const float* ext) {
    switch (id) {
        case 0: return g_xn;   case 1: return g_u;    case 2: return g_a1;
        case 3: return g_a2;   case 4: return g_off;  case 5: return g_a3;
        case 6: return g_skip; case 7: return g_h1;   case 8: return g_attn;
    }
    return (float*)ext;
}

// ---------------- fused LayerNorm + proj_1 + GELU ----------------
__global__ void __launch_bounds__(256) k_lnpw(
    const float* __restrict__ x,
    const float* __restrict__ ls, const float* __restrict__ lb,
    const float* __restrict__ w,  const float* __restrict__ bias)
{
    __shared__ __align__(16) float ws2[CC * CC];   // [c][o], o contiguous
    __shared__ float bs[CC];
    for (int i = threadIdx.x; i < CC * CC; i += blockDim.x) {
        int o = i / CC, c = i - o * CC;
        ws2[c * CC + o] = w[i];
    }
    if (threadIdx.x < CC) bs[threadIdx.x] = bias[threadIdx.x];
    __syncthreads();

    int i = blockIdx.x * blockDim.x + threadIdx.x;
    int b = i >> 15, s = i & (SS - 1);
    const float* xb = x + (size_t)b * CC * SS + s;

    float s1 = 0.f, s2 = 0.f;
    #pragma unroll 8
    for (int c = 0; c < CC; c++) { float v = xb[c * SS]; s1 += v; s2 += v * v; }
    float mu  = s1 * (1.f / CC);
    float var = s2 * (1.f / CC) - mu * mu;
    float inv = rsqrtf(var + 1e-5f);

    float* xnp = g_xn + (size_t)b * CC * SS + s;

    ull acc2[CC / 2];
    #pragma unroll
    for (int q = 0; q < CC / 2; q++) acc2[q] = 0ull;

    const ulonglong2* wrow = (const ulonglong2*)ws2;
    #pragma unroll 4
    for (int c = 0; c < CC; c++) {
        float v = (xb[c * SS] - mu) * inv * ls[c] + lb[c];
        xnp[c * SS] = v;
        ull vv = pack2(v, v);
        #pragma unroll
        for (int q = 0; q < CC / 4; q++) {
            ulonglong2 wq = wrow[c * (CC / 4) + q];
            fma2(acc2[2 * q + 0], wq.x, vv);
            fma2(acc2[2 * q + 1], wq.y, vv);
        }
    }

    float* up = g_u + (size_t)b * CC * SS + s;
    #pragma unroll
    for (int q = 0; q < CC / 2; q++) {
        float a0, a1;
        unpack2(a0, a1, acc2[q]);
        float v0 = a0 + bs[2 * q + 0];
        float v1 = a1 + bs[2 * q + 1];
        up[(2 * q + 0) * SS] = 0.5f * v0 * (1.f + erff(v0 * 0.70710678118654752f));
        up[(2 * q + 1) * SS] = 0.5f * v1 * (1.f + erff(v1 * 0.70710678118654752f));
    }
}

// ---------------- fused c1 + gate + p2 + residual ----------------
// t    = c1_w @ (a3+h1+attn partials + dc_b) + c1_b
// gate = u * t
// skip = x + gamma * (p2_w @ gate + p2_b + xn)
__global__ void __launch_bounds__(256) k_pwgate(
    const float* __restrict__ c1w, const float* __restrict__ c1b,
    const float* __restrict__ dcb,
    const float* __restrict__ p2w, const float* __restrict__ p2b,
    const float* __restrict__ x,   const float* __restrict__ gamma)
{
    __shared__ __align__(16) float ws1[CC * CC];   // c1: [c][o]
    __shared__ __align__(16) float wsp[CC * CC];   // p2: [c][o]
    __shared__ float bs1[CC], dcs[CC], bs2[CC], gm[CC];
    for (int i = threadIdx.x; i < CC * CC; i += blockDim.x) {
        int o = i / CC, c = i - o * CC;
        ws1[c * CC + o] = c1w[i];
        wsp[c * CC + o] = p2w[i];
    }
    if (threadIdx.x < CC) {
        bs1[threadIdx.x] = c1b[threadIdx.x];
        dcs[threadIdx.x] = dcb[threadIdx.x];
        bs2[threadIdx.x] = p2b[threadIdx.x];
        gm[threadIdx.x]  = gamma[threadIdx.x];
    }
    __syncthreads();

    int i = blockIdx.x * blockDim.x + threadIdx.x;
    int b = i >> 15, s = i & (SS - 1);
    size_t base = (size_t)b * CC * SS + s;
    const float* in  = g_a3  + base;
    const float* pp1 = g_h1  + base;
    const float* pp2 = g_attn + base;
    const float* up  = g_u   + base;
    const float* xnp = g_xn  + base;
    const float* xp  = x + base;

    // GEMM1: c1 on summed partials
    ull acc2[CC / 2];
    #pragma unroll
    for (int q = 0; q < CC / 2; q++) acc2[q] = 0ull;
    const ulonglong2* w1 = (const ulonglong2*)ws1;
    #pragma unroll 4
    for (int c = 0; c < CC; c++) {
        float v = in[c * SS] + pp1[c * SS] + pp2[c * SS] + dcs[c];
        ull vv = pack2(v, v);
        #pragma unroll
        for (int q = 0; q < CC / 4; q++) {
            ulonglong2 wq = w1[c * (CC / 4) + q];
            fma2(acc2[2 * q + 0], wq.x, vv);
            fma2(acc2[2 * q + 1], wq.y, vv);
        }
    }
    // gate values
    float t[CC];
    #pragma unroll
    for (int q = 0; q < CC / 2; q++) unpack2(t[2 * q], t[2 * q + 1], acc2[q]);
    #pragma unroll
    for (int o = 0; o < CC; o++) t[o] = up[o * SS] * (t[o] + bs1[o]);

    // GEMM2: p2 on gate
    #pragma unroll
    for (int q = 0; q < CC / 2; q++) acc2[q] = 0ull;
    const ulonglong2* w2 = (const ulonglong2*)wsp;
    #pragma unroll 4
    for (int c = 0; c < CC; c++) {
        ull vv = pack2(t[c], t[c]);
        #pragma unroll
        for (int q = 0; q < CC / 4; q++) {
            ulonglong2 wq = w2[c * (CC / 4) + q];
            fma2(acc2[2 * q + 0], wq.x, vv);
            fma2(acc2[2 * q + 1], wq.y, vv);
        }
    }

    float* skp = g_skip + base;
    #pragma unroll
    for (int q = 0; q < CC / 2; q++) {
        float a0, a1;
        unpack2(a0, a1, acc2[q]);
        int o0 = 2 * q, o1 = 2 * q + 1;
        skp[o0 * SS] = xp[o0 * SS] + gm[o0] * (a0 + bs2[o0] + xnp[o0 * SS]);
        skp[o1 * SS] = xp[o1 * SS] + gm[o1] * (a1 + bs2[o1] + xnp[o1 * SS]);
    }
}

// ---------------- 1x1x1 pointwise 48x48 (final projconv only) ----------------
// out = aux1 + acc + bias[o]
__global__ void __launch_bounds__(256) k_pw48(
    int in_id, const float* __restrict__ w, const float* __restrict__ bias,
    int a1_id, float* __restrict__ ext_out)
{
    __shared__ __align__(16) float ws2[CC * CC];   // [c][o], o contiguous
    __shared__ float bs[CC];
    for (int i = threadIdx.x; i < CC * CC; i += blockDim.x) {
        int o = i / CC, c = i - o * CC;
        ws2[c * CC + o] = w[i];
    }
    if (threadIdx.x < CC) bs[threadIdx.x] = bias[threadIdx.x];
    __syncthreads();

    int i = blockIdx.x * blockDim.x + threadIdx.x;
    int b = i >> 15, s = i & (SS - 1);
    size_t base = (size_t)b * CC * SS + s;
    const float* in = bufsel(in_id, nullptr) + base;

    ull acc2[CC / 2];
    #pragma unroll
    for (int q = 0; q < CC / 2; q++) acc2[q] = 0ull;

    const ulonglong2* wrow = (const ulonglong2*)ws2;
    #pragma unroll 4
    for (int c = 0; c < CC; c++) {
        float v = in[c * SS];
        ull vv = pack2(v, v);
        #pragma unroll
        for (int q = 0; q < CC / 4; q++) {
            ulonglong2 wq = wrow[c * (CC / 4) + q];
            fma2(acc2[2 * q + 0], wq.x, vv);
            fma2(acc2[2 * q + 1], wq.y, vv);
        }
    }

    float* outp = ext_out + base;
    const float* a1p = bufsel(a1_id, nullptr) + base;
    #pragma unroll
    for (int q = 0; q < CC / 2; q++) {
        float a0, a1;
        unpack2(a0, a1, acc2[q]);
        outp[(2 * q + 0) * SS] = a1p[(2 * q + 0) * SS] + a0 + bs[2 * q + 0];
        outp[(2 * q + 1) * SS] = a1p[(2 * q + 1) * SS] + a1 + bs[2 * q + 1];
    }
}

// ---------------- depthwise KxKxK: 4 x-adjacent outputs/thread, float4 rows ----------------
template<int K, int PAD, int DIL>
__global__ void __launch_bounds__(256) k_dw(int in_id, const float* __restrict__ w,
                                            const float* __restrict__ bias, int out_id) {
    constexpr int LOW = -(((PAD) + 3) / 4) * 4;
    constexpr int HI  = 3 + (K - 1) * DIL - PAD;
    constexpr int NCH = (HI - LOW) / 4 + 1;
    __shared__ float ws[K * K * K];
    int c = blockIdx.y, b = blockIdx.z;
    for (int i = threadIdx.x; i < K * K * K; i += blockDim.x)
        ws[i] = w[c * K * K * K + i];
    __syncthreads();
    int s = blockIdx.x * 1024 + threadIdx.x * 4;
    int z = s >> 10, y = (s >> 5) & 31, x0 = s & 31;
    const float* ib = bufsel(in_id, nullptr) + ((size_t)b * CC + c) * SS;

    float b0 = bias[c];
    float acc[4] = {b0, b0, b0, b0};

    #pragma unroll
    for (int i = 0; i < K; i++) {
        int zz = z + i * DIL - PAD;
        if ((unsigned)zz >= 32u) continue;
        #pragma unroll
        for (int j = 0; j < K; j++) {
            int yy = y + j * DIL - PAD;
            if ((unsigned)yy >= 32u) continue;
            const float* row = ib + (zz << 10) + (yy << 5);
            float v[NCH * 4];
            #pragma unroll
            for (int ch = 0; ch < NCH; ch++) {
                int xb = x0 + LOW + ch * 4;
                if (xb >= 0 && xb <= 28) {
                    float4 t = *(const float4*)(row + xb);
                    v[ch * 4 + 0] = t.x; v[ch * 4 + 1] = t.y;
                    v[ch * 4 + 2] = t.z; v[ch * 4 + 3] = t.w;
                } else {
                    v[ch * 4 + 0] = 0.f; v[ch * 4 + 1] = 0.f;
                    v[ch * 4 + 2] = 0.f; v[ch * 4 + 3] = 0.f;
                }
            }
            const float* wr = ws + (i * K + j) * K;
            #pragma unroll
            for (int l = 0; l < K; l++) {
                float wv = wr[l];
                #pragma unroll
                for (int u = 0; u < 4; u++)
                    acc[u] += wv * v[u + l * DIL - PAD - LOW];
            }
        }
    }
    float* op = bufsel(out_id, nullptr) + ((size_t)b * CC + c) * SS + s;
    *(float4*)op = make_float4(acc[0], acc[1], acc[2], acc[3]);
}

// ---------------- dense 3x3x3 conv, 2 voxels/thread, row-streamed, f32x2 ----------------
// mode 0: +bias; 1: leaky(bn); 2: leaky(bn + skip)
template<int NO, int NO4, int CCH>
__global__ void __launch_bounds__(256, 2) k_c3g(
    int in_id, const float* __restrict__ w,
    const float* __restrict__ bias,
    const float* __restrict__ bs2, const float* __restrict__ bbp,
    const float* __restrict__ bm, const float* __restrict__ bv,
    int skip_id, int out_id, int O, int mode)
{
    __shared__ __align__(16) float ws[CCH * 27 * NO4];
    const int o0 = blockIdx.y * NO;
    const int b  = blockIdx.z;
    const int s  = blockIdx.x * 512 + threadIdx.x * 2;
    const int z = s >> 10, y = (s >> 5) & 31, x0 = s & 31;
    const float* ib = bufsel(in_id, nullptr) + (size_t)b * CC * SS;

    ull accA[NO4 / 2], accB[NO4 / 2];
    #pragma unroll
    for (int q = 0; q < NO4 / 2; q++) { accA[q] = 0ull; accB[q] = 0ull; }

    for (int cbase = 0; cbase < CC; cbase += CCH) {
        __syncthreads();
        for (int gidx = threadIdx.x; gidx < NO * CCH * 27; gidx += blockDim.x) {
            int oL  = gidx / (CCH * 27);
            int r   = gidx - oL * (CCH * 27);
            int cL  = r / 27;
            int tap = r - cL * 27;
            ws[(cL * 27 + tap) * NO4 + oL] =
                w[(size_t)(o0 + oL) * (CC * 27) + (cbase + cL) * 27 + tap];
        }
        __syncthreads();

        for (int cL = 0; cL < CCH; cL++) {
            const float* ic = ib + (cbase + cL) * SS;
            const ulonglong2* wbase = (const ulonglong2*)(ws + cL * 27 * NO4);
            #pragma unroll
            for (int kd = 0; kd < 3; kd++) {
                int zz = z + kd - 1; bool vz = (unsigned)zz < 32u;
                #pragma unroll
                for (int kh = 0; kh < 3; kh++) {
                    int yy = y + kh - 1; bool vy = (unsigned)yy < 32u;
                    int rbase = (zz << 10) + (yy << 5);
                    bool vzy = vz && vy;
                    float r0 = (vzy && x0 >= 1)  ? ic[rbase + x0 - 1] : 0.f;
                    float r1 =  vzy              ? ic[rbase + x0    ] : 0.f;
                    float r2 =  vzy              ? ic[rbase + x0 + 1] : 0.f;
                    float r3 = (vzy && x0 <= 29) ? ic[rbase + x0 + 2] : 0.f;
                    int taprow = (kd * 3 + kh) * 3;
                    #pragma unroll
                    for (int kw = 0; kw < 3; kw++) {
                        float vA = (kw == 0) ? r0 : (kw == 1) ? r1 : r2;
                        float vB = (kw == 0) ? r1 : (kw == 1) ? r2 : r3;
                        ull vvA = pack2(vA, vA);
                        ull vvB = pack2(vB, vB);
                        const ulonglong2* wrow = wbase + (taprow + kw) * (NO4 / 4);
                        #pragma unroll
                        for (int q = 0; q < NO4 / 4; q++) {
                            ulonglong2 wq = wrow[q];
                            fma2(accA[2 * q + 0], wq.x, vvA);
                            fma2(accA[2 * q + 1], wq.y, vvA);
                            fma2(accB[2 * q + 0], wq.x, vvB);
                            fma2(accB[2 * q + 1], wq.y, vvB);
                        }
                    }
                }
            }
        }
    }

    float aA[NO4], aB[NO4];
    #pragma unroll
    for (int q = 0; q < NO4 / 2; q++) {
        unpack2(aA[2 * q], aA[2 * q + 1], accA[q]);
        unpack2(aB[2 * q], aB[2 * q + 1], accB[q]);
    }

    float* outb = bufsel(out_id, nullptr) + (size_t)b * O * SS + s;
    if (mode == 0) {
        #pragma unroll
        for (int o = 0; o < NO; o++) {
            float bb = bias[o0 + o];
            *(float2*)&outb[(o0 + o) * SS] = make_float2(aA[o] + bb, aB[o] + bb);
        }
    } else {
        const float* skp = (mode == 2) ? bufsel(skip_id, nullptr) + (size_t)b * O * SS + s
                                       : nullptr;
        #pragma unroll
        for (int o = 0; o < NO; o++) {
            int og = o0 + o;
            float scale = bs2[og] * rsqrtf(bv[og] + 1e-5f);
            float sh = bbp[og] - bm[og] * scale;
            float hA = aA[o] * scale + sh;
            float hB = aB[o] * scale + sh;
            if (mode == 2) { hA += skp[og * SS]; hB += skp[og * SS + 1]; }
            hA = (hA >= 0.f) ? hA : 0.01f * hA;
            hB = (hB >= 0.f) ? hB : 0.01f * hB;
            *(float2*)&outb[og * SS] = make_float2(hA, hB);
        }
    }
}

// ---------------- transpose dc_w [o][c][k] -> [k][c][o] ----------------
__global__ void k_wt(const float* __restrict__ w) {
    int i = blockIdx.x * blockDim.x + threadIdx.x;
    if (i >= CC * CC * 27) return;
    int o = i / (CC * 27);
    int r = i - o * (CC * 27);
    int c = r / 27;
    int k = r - c * 27;
    g_dcwt[(k * CC + c) * CC + o] = w[i];
}

// ---------------- deformable conv: 3-way tap split, 3-tap smem staging, f32x2 ----------------
__global__ void __launch_bounds__(256, 2) k_deform() {
    __shared__ __align__(16) float wt_s[3][CC * CC];   // [tap-in-triple][c][o]
    int s = blockIdx.x * blockDim.x + threadIdx.x;
    int b = blockIdx.y;
    int g = blockIdx.z;
    int z = s >> 10, y = (s >> 5) & 31, x = s & 31;
    const float* a   = g_a2  + (size_t)b * CC * SS;
    const float* off = g_off + (size_t)b * OFFC * SS + s;

    ull acc2[CC / 2];
    #pragma unroll
    for (int q = 0; q < CC / 2; q++) acc2[q] = 0ull;

    #pragma unroll 1
    for (int kt0 = g * 9; kt0 < g * 9 + 9; kt0 += 3) {
        __syncthreads();
        {
            const float4* src = (const float4*)(g_dcwt + kt0 * CC * CC);
            float4* dst = (float4*)wt_s[0];
            for (int i = threadIdx.x; i < 3 * CC * CC / 4; i += blockDim.x)
                dst[i] = src[i];
        }
        __syncthreads();

        #pragma unroll 1
        for (int tloc = 0; tloc < 3; tloc++) {
            int kt = kt0 + tloc;
            int kd = kt / 9 - 1, kh = (kt / 3) % 3 - 1, kw = kt % 3 - 1;
            float zf = (float)(z + kd) + off[(kt * 3 + 0) * SS];
            float yf = (float)(y + kh) + off[(kt * 3 + 1) * SS];
            float xf = (float)(x + kw) + off[(kt * 3 + 2) * SS];
            float z0 = floorf(zf), y0 = floorf(yf), x0 = floorf(xf);
            float tz = zf - z0, ty = yf - y0, tx = xf - x0;
            int iz0 = (int)z0, iy0 = (int)y0, ix0 = (int)x0;

            int idx8[8];
            ull w8v[8];
            #pragma unroll
            for (int dz = 0; dz < 2; dz++)
            #pragma unroll
            for (int dy = 0; dy < 2; dy++)
            #pragma unroll
            for (int dx = 0; dx < 2; dx++) {
                int j = dz * 4 + dy * 2 + dx;
                int zi = iz0 + dz, yi = iy0 + dy, xi = ix0 + dx;
                bool valid = (zi >= 0 && zi < 32 && yi >= 0 && yi < 32 && xi >= 0 && xi < 32);
                float wg = (dz ? tz : 1.f - tz) * (dy ? ty : 1.f - ty) * (dx ? tx : 1.f - tx);
                int zc = min(max(zi, 0), 31), yc = min(max(yi, 0), 31), xc = min(max(xi, 0), 31);
                idx8[j] = (zc << 10) + (yc << 5) + xc;
                float wf = valid ? wg : 0.f;
                w8v[j] = pack2(wf, wf);
            }

            const float* wts = wt_s[tloc];
            for (int c = 0; c < CC; c += 2) {
                const float* ac0 = a + c * SS;
                const float* ac1 = ac0 + SS;
                ull valv = 0ull;
                #pragma unroll
                for (int j = 0; j < 8; j++)
                    fma2(valv, pack2(ac0[idx8[j]], ac1[idx8[j]]), w8v[j]);
                float v0, v1;
                unpack2(v0, v1, valv);
                ull vv0 = pack2(v0, v0), vv1 = pack2(v1, v1);

                const ulonglong2* w0 = (const ulonglong2*)(wts + (c + 0) * CC);
                const ulonglong2* w1 = (const ulonglong2*)(wts + (c + 1) * CC);
                #pragma unroll
                for (int q = 0; q < CC / 4; q++) {
                    ulonglong2 wa = w0[q];
                    fma2(acc2[2 * q + 0], wa.x, vv0);
                    fma2(acc2[2 * q + 1], wa.y, vv0);
                }
                #pragma unroll
                for (int q = 0; q < CC / 4; q++) {
                    ulonglong2 wb = w1[q];
                    fma2(acc2[2 * q + 0], wb.x, vv1);
                    fma2(acc2[2 * q + 1], wb.y, vv1);
                }
            }
        }
    }

    int outid = (g == 0) ? 5 : (g == 1) ? 7 : 8;
    float* ob = bufsel(outid, nullptr) + (size_t)b * CC * SS + s;
    #pragma unroll
    for (int q = 0; q < CC / 2; q++) {
        float a0, a1;
        unpack2(a0, a1, acc2[q]);
        ob[(2 * q + 0) * SS] = a0;
        ob[(2 * q + 1) * SS] = a1;
    }
}

// ---------------- launch: kernel launches ONLY ----------------
extern "C" void kernel_launch(void* const* d_in, const int* in_sizes, int n_in,
                              void* d_out, int out_size) {
    const float* x     = (const float*)d_in[0];
    const float* ln_s  = (const float*)d_in[1];
    const float* ln_b  = (const float*)d_in[2];
    const float* gamma = (const float*)d_in[3];
    const float* p1_w  = (const float*)d_in[4];
    const float* p1_b  = (const float*)d_in[5];
    const float* p2_w  = (const float*)d_in[6];
    const float* p2_b  = (const float*)d_in[7];
    const float* c0_w  = (const float*)d_in[8];
    const float* c0_b  = (const float*)d_in[9];
    const float* cs_w  = (const float*)d_in[10];
    const float* cs_b  = (const float*)d_in[11];
    const float* off_w = (const float*)d_in[12];
    const float* off_b = (const float*)d_in[13];
    const float* dc_w  = (const float*)d_in[14];
    const float* dc_b  = (const float*)d_in[15];
    const float* c1_w  = (const float*)d_in[16];
    const float* c1_b  = (const float*)d_in[17];
    const float* u1_w  = (const float*)d_in[18];
    const float* bn1_s = (const float*)d_in[19];
    const float* bn1_b = (const float*)d_in[20];
    const float* bn1_m = (const float*)d_in[21];
    const float* bn1_v = (const float*)d_in[22];
    const float* u2_w  = (const float*)d_in[23];
    const float* bn2_s = (const float*)d_in[24];
    const float* bn2_b = (const float*)d_in[25];
    const float* bn2_m = (const float*)d_in[26];
    const float* bn2_v = (const float*)d_in[27];
    const float* pr_w  = (const float*)d_in[28];
    const float* pr_b  = (const float*)d_in[29];
    float* out = (float*)d_out;

    dim3 pwGrid((BB * SS) / 256);
    dim3 dwGrid(SS / 1024, CC, BB);
    dim3 c3OffGrid(SS / 512, 3, BB);
    dim3 c3UGrid(SS / 512, 2, BB);

    // 1. fused LayerNorm + proj_1 + GELU: x -> g_xn (0), g_u (1)
    k_lnpw<<<pwGrid, 256>>>(x, ln_s, ln_b, p1_w, p1_b);
    // 2. depthwise 5x5x5 pad 2: g_u -> g_a1 (2)
    k_dw<5, 2, 1><<<dwGrid, 256>>>(1, c0_w, c0_b, 2);
    // 3. depthwise 7x7x7 dil 3 pad 9: g_a1 -> g_a2 (3)
    k_dw<7, 9, 3><<<dwGrid, 256>>>(2, cs_w, cs_b, 3);
    // 4. offset conv 3x3x3 -> 81 channels: g_a2 -> g_off (4)
    k_c3g<27, 28, 8><<<c3OffGrid, 256>>>(3, off_w, off_b,
                                         nullptr, nullptr, nullptr, nullptr,
                                         -1, 4, OFFC, 0);
    // 5. transpose deform weights
    k_wt<<<(CC * CC * 27 + 255) / 256, 256>>>(dc_w);
    // 6. deformable conv, 3 tap groups: partials -> g_a3 (5), g_h1 (7), g_attn (8)
    k_deform<<<dim3(SS / 256, BB, 3), 256>>>();
    // 7+8 fused: c1 GEMM on (partials + dc_b), gate by g_u, p2 GEMM,
    //            skip = x + gamma*(p2 + p2_b + g_xn) -> g_skip (6)
    k_pwgate<<<pwGrid, 256>>>(c1_w, c1_b, dc_b, p2_w, p2_b, x, gamma);
    // 9. u1 conv3 + BN1 + leaky: g_skip -> g_h1 (7)
    k_c3g<24, 24, 8><<<c3UGrid, 256>>>(6, u1_w, nullptr,
                                       bn1_s, bn1_b, bn1_m, bn1_v,
                                       -1, 7, CC, 1);
    // 10. u2 conv3 + BN2 + skip + leaky: g_h1 -> g_attn (8)
    k_c3g<24, 24, 8><<<c3UGrid, 256>>>(7, u2_w, nullptr,
                                       bn2_s, bn2_b, bn2_m, bn2_v,
                                       6, 8, CC, 2);
    // 11. projconv 1x1x1 + skip -> out (external)
    k_pw48<<<pwGrid, 256>>>(8, pr_w, pr_b, 6, out);
}

// round 17
// speedup vs baseline: 1.0578x; 1.0079x over previous
#include <cuda_runtime.h>
#include <math.h>

// Problem constants (B=2, C=48, 32^3 volume)
#define BB   2
#define CC   48
#define SS   (32*32*32)          // 32768
#define OFFC 81

typedef unsigned long long ull;

// ---------------- f32x2 packed helpers (sm_100+) ----------------
__device__ __forceinline__ ull pack2(float a, float b) {
    ull r;
    asm("mov.b64 %0, {%1, %2};" : "=l"(r) : "f"(a), "f"(b));
    return r;
}
__device__ __forceinline__ void fma2(ull& d, ull a, ull b) {
    asm("fma.rn.f32x2 %0, %1, %2, %0;" : "+l"(d) : "l"(a), "l"(b));
}
__device__ __forceinline__ void unpack2(float& lo, float& hi, ull v) {
    asm("mov.b64 {%0, %1}, %2;" : "=f"(lo), "=f"(hi) : "l"(v));
}

// ---------------- scratch (device globals; allocation-free) ----------------
__device__ float g_xn  [BB*CC*SS];   // 0
__device__ float g_u   [BB*CC*SS];   // 1
__device__ float g_a1  [BB*CC*SS];   // 2
__device__ float g_a2  [BB*CC*SS];   // 3
__device__ float g_off [BB*OFFC*SS]; // 4
__device__ float g_a3  [BB*CC*SS];   // 5  (deform partial 0)
__device__ float g_skip[BB*CC*SS];   // 6
__device__ float g_h1  [BB*CC*SS];   // 7  (deform partial 1, later u1 out)
__device__ float g_attn[BB*CC*SS];   // 8  (deform partial 2, later u2 out)
__device__ float g_dcwt[27*CC*CC];   // dc_w transposed to [tap][c][o]

__device__ __forceinline__ float* bufsel(int id, const float* ext) {
    switch (id) {
        case 0: return g_xn;   case 1: return g_u;    case 2: return g_a1;
        case 3: return g_a2;   case 4: return g_off;  case 5: return g_a3;
        case 6: return g_skip; case 7: return g_h1;   case 8: return g_attn;
    }
    return (float*)ext;
}

// ---------------- fused LayerNorm + proj_1 + GELU ----------------
__global__ void __launch_bounds__(256) k_lnpw(
    const float* __restrict__ x,
    const float* __restrict__ ls, const float* __restrict__ lb,
    const float* __restrict__ w,  const float* __restrict__ bias)
{
    __shared__ __align__(16) float ws2[CC * CC];   // [c][o], o contiguous
    __shared__ float bs[CC];
    for (int i = threadIdx.x; i < CC * CC; i += blockDim.x) {
        int o = i / CC, c = i - o * CC;
        ws2[c * CC + o] = w[i];
    }
    if (threadIdx.x < CC) bs[threadIdx.x] = bias[threadIdx.x];
    __syncthreads();

    int i = blockIdx.x * blockDim.x + threadIdx.x;
    int b = i >> 15, s = i & (SS - 1);
    const float* xb = x + (size_t)b * CC * SS + s;

    float s1 = 0.f, s2 = 0.f;
    #pragma unroll 8
    for (int c = 0; c < CC; c++) { float v = xb[c * SS]; s1 += v; s2 += v * v; }
    float mu  = s1 * (1.f / CC);
    float var = s2 * (1.f / CC) - mu * mu;
    float inv = rsqrtf(var + 1e-5f);

    float* xnp = g_xn + (size_t)b * CC * SS + s;

    ull acc2[CC / 2];
    #pragma unroll
    for (int q = 0; q < CC / 2; q++) acc2[q] = 0ull;

    const ulonglong2* wrow = (const ulonglong2*)ws2;
    #pragma unroll 4
    for (int c = 0; c < CC; c++) {
        float v = (xb[c * SS] - mu) * inv * ls[c] + lb[c];
        xnp[c * SS] = v;
        ull vv = pack2(v, v);
        #pragma unroll
        for (int q = 0; q < CC / 4; q++) {
            ulonglong2 wq = wrow[c * (CC / 4) + q];
            fma2(acc2[2 * q + 0], wq.x, vv);
            fma2(acc2[2 * q + 1], wq.y, vv);
        }
    }

    float* up = g_u + (size_t)b * CC * SS + s;
    #pragma unroll
    for (int q = 0; q < CC / 2; q++) {
        float a0, a1;
        unpack2(a0, a1, acc2[q]);
        float v0 = a0 + bs[2 * q + 0];
        float v1 = a1 + bs[2 * q + 1];
        up[(2 * q + 0) * SS] = 0.5f * v0 * (1.f + erff(v0 * 0.70710678118654752f));
        up[(2 * q + 1) * SS] = 0.5f * v1 * (1.f + erff(v1 * 0.70710678118654752f));
    }
}

// ---------------- fused c1 + gate + p2 + residual ----------------
__global__ void __launch_bounds__(256) k_pwgate(
    const float* __restrict__ c1w, const float* __restrict__ c1b,
    const float* __restrict__ dcb,
    const float* __restrict__ p2w, const float* __restrict__ p2b,
    const float* __restrict__ x,   const float* __restrict__ gamma)
{
    __shared__ __align__(16) float ws1[CC * CC];   // c1: [c][o]
    __shared__ __align__(16) float wsp[CC * CC];   // p2: [c][o]
    __shared__ float bs1[CC], dcs[CC], bs2[CC], gm[CC];
    for (int i = threadIdx.x; i < CC * CC; i += blockDim.x) {
        int o = i / CC, c = i - o * CC;
        ws1[c * CC + o] = c1w[i];
        wsp[c * CC + o] = p2w[i];
    }
    if (threadIdx.x < CC) {
        bs1[threadIdx.x] = c1b[threadIdx.x];
        dcs[threadIdx.x] = dcb[threadIdx.x];
        bs2[threadIdx.x] = p2b[threadIdx.x];
        gm[threadIdx.x]  = gamma[threadIdx.x];
    }
    __syncthreads();

    int i = blockIdx.x * blockDim.x + threadIdx.x;
    int b = i >> 15, s = i & (SS - 1);
    size_t base = (size_t)b * CC * SS + s;
    const float* in  = g_a3  + base;
    const float* pp1 = g_h1  + base;
    const float* pp2 = g_attn + base;
    const float* up  = g_u   + base;
    const float* xnp = g_xn  + base;
    const float* xp  = x + base;

    ull acc2[CC / 2];
    #pragma unroll
    for (int q = 0; q < CC / 2; q++) acc2[q] = 0ull;
    const ulonglong2* w1 = (const ulonglong2*)ws1;
    #pragma unroll 4
    for (int c = 0; c < CC; c++) {
        float v = in[c * SS] + pp1[c * SS] + pp2[c * SS] + dcs[c];
        ull vv = pack2(v, v);
        #pragma unroll
        for (int q = 0; q < CC / 4; q++) {
            ulonglong2 wq = w1[c * (CC / 4) + q];
            fma2(acc2[2 * q + 0], wq.x, vv);
            fma2(acc2[2 * q + 1], wq.y, vv);
        }
    }
    float t[CC];
    #pragma unroll
    for (int q = 0; q < CC / 2; q++) unpack2(t[2 * q], t[2 * q + 1], acc2[q]);
    #pragma unroll
    for (int o = 0; o < CC; o++) t[o] = up[o * SS] * (t[o] + bs1[o]);

    #pragma unroll
    for (int q = 0; q < CC / 2; q++) acc2[q] = 0ull;
    const ulonglong2* w2 = (const ulonglong2*)wsp;
    #pragma unroll 4
    for (int c = 0; c < CC; c++) {
        ull vv = pack2(t[c], t[c]);
        #pragma unroll
        for (int q = 0; q < CC / 4; q++) {
            ulonglong2 wq = w2[c * (CC / 4) + q];
            fma2(acc2[2 * q + 0], wq.x, vv);
            fma2(acc2[2 * q + 1], wq.y, vv);
        }
    }

    float* skp = g_skip + base;
    #pragma unroll
    for (int q = 0; q < CC / 2; q++) {
        float a0, a1;
        unpack2(a0, a1, acc2[q]);
        int o0 = 2 * q, o1 = 2 * q + 1;
        skp[o0 * SS] = xp[o0 * SS] + gm[o0] * (a0 + bs2[o0] + xnp[o0 * SS]);
        skp[o1 * SS] = xp[o1 * SS] + gm[o1] * (a1 + bs2[o1] + xnp[o1 * SS]);
    }
}

// ---------------- 1x1x1 pointwise 48x48 (final projconv only) ----------------
__global__ void __launch_bounds__(256) k_pw48(
    int in_id, const float* __restrict__ w, const float* __restrict__ bias,
    int a1_id, float* __restrict__ ext_out)
{
    __shared__ __align__(16) float ws2[CC * CC];
    __shared__ float bs[CC];
    for (int i = threadIdx.x; i < CC * CC; i += blockDim.x) {
        int o = i / CC, c = i - o * CC;
        ws2[c * CC + o] = w[i];
    }
    if (threadIdx.x < CC) bs[threadIdx.x] = bias[threadIdx.x];
    __syncthreads();

    int i = blockIdx.x * blockDim.x + threadIdx.x;
    int b = i >> 15, s = i & (SS - 1);
    size_t base = (size_t)b * CC * SS + s;
    const float* in = bufsel(in_id, nullptr) + base;

    ull acc2[CC / 2];
    #pragma unroll
    for (int q = 0; q < CC / 2; q++) acc2[q] = 0ull;

    const ulonglong2* wrow = (const ulonglong2*)ws2;
    #pragma unroll 4
    for (int c = 0; c < CC; c++) {
        float v = in[c * SS];
        ull vv = pack2(v, v);
        #pragma unroll
        for (int q = 0; q < CC / 4; q++) {
            ulonglong2 wq = wrow[c * (CC / 4) + q];
            fma2(acc2[2 * q + 0], wq.x, vv);
            fma2(acc2[2 * q + 1], wq.y, vv);
        }
    }

    float* outp = ext_out + base;
    const float* a1p = bufsel(a1_id, nullptr) + base;
    #pragma unroll
    for (int q = 0; q < CC / 2; q++) {
        float a0, a1;
        unpack2(a0, a1, acc2[q]);
        outp[(2 * q + 0) * SS] = a1p[(2 * q + 0) * SS] + a0 + bs[2 * q + 0];
        outp[(2 * q + 1) * SS] = a1p[(2 * q + 1) * SS] + a1 + bs[2 * q + 1];
    }
}

// ---------------- depthwise KxKxK: 4 x-adjacent outputs/thread, float4 rows ----------------
template<int K, int PAD, int DIL>
__global__ void __launch_bounds__(256) k_dw(int in_id, const float* __restrict__ w,
                                            const float* __restrict__ bias, int out_id) {
    constexpr int LOW = -(((PAD) + 3) / 4) * 4;
    constexpr int HI  = 3 + (K - 1) * DIL - PAD;
    constexpr int NCH = (HI - LOW) / 4 + 1;
    __shared__ float ws[K * K * K];
    int c = blockIdx.y, b = blockIdx.z;
    for (int i = threadIdx.x; i < K * K * K; i += blockDim.x)
        ws[i] = w[c * K * K * K + i];
    __syncthreads();
    int s = blockIdx.x * 1024 + threadIdx.x * 4;
    int z = s >> 10, y = (s >> 5) & 31, x0 = s & 31;
    const float* ib = bufsel(in_id, nullptr) + ((size_t)b * CC + c) * SS;

    float b0 = bias[c];
    float acc[4] = {b0, b0, b0, b0};

    #pragma unroll
    for (int i = 0; i < K; i++) {
        int zz = z + i * DIL - PAD;
        if ((unsigned)zz >= 32u) continue;
        #pragma unroll
        for (int j = 0; j < K; j++) {
            int yy = y + j * DIL - PAD;
            if ((unsigned)yy >= 32u) continue;
            const float* row = ib + (zz << 10) + (yy << 5);
            float v[NCH * 4];
            #pragma unroll
            for (int ch = 0; ch < NCH; ch++) {
                int xb = x0 + LOW + ch * 4;
                if (xb >= 0 && xb <= 28) {
                    float4 t = *(const float4*)(row + xb);
                    v[ch * 4 + 0] = t.x; v[ch * 4 + 1] = t.y;
                    v[ch * 4 + 2] = t.z; v[ch * 4 + 3] = t.w;
                } else {
                    v[ch * 4 + 0] = 0.f; v[ch * 4 + 1] = 0.f;
                    v[ch * 4 + 2] = 0.f; v[ch * 4 + 3] = 0.f;
                }
            }
            const float* wr = ws + (i * K + j) * K;
            #pragma unroll
            for (int l = 0; l < K; l++) {
                float wv = wr[l];
                #pragma unroll
                for (int u = 0; u < 4; u++)
                    acc[u] += wv * v[u + l * DIL - PAD - LOW];
            }
        }
    }
    float* op = bufsel(out_id, nullptr) + ((size_t)b * CC + c) * SS + s;
    *(float4*)op = make_float4(acc[0], acc[1], acc[2], acc[3]);
}

// ---------------- dense 3x3x3 conv: 4 voxels/thread x NO=12 outputs ----------------
// Per tap: 3 LDS.128 feed 24 fma2 (ratio 8). acc = 24 ull = 48 regs ->
// __launch_bounds__(256,3) targets 3 blocks/SM (24 warps).
// Row x-window (x0-1..x0+4, x0 % 4 == 0): 1 aligned float4 + 2 predicated scalars.
// mode 0: +bias (guarded); 1: leaky(bn); 2: leaky(bn + skip)
template<int NO, int CCH>
__global__ void __launch_bounds__(256, 3) k_c3g(
    int in_id, const float* __restrict__ w,
    const float* __restrict__ bias,
    const float* __restrict__ bs2, const float* __restrict__ bbp,
    const float* __restrict__ bm, const float* __restrict__ bv,
    int skip_id, int out_id, int O, int mode)
{
    __shared__ __align__(16) float ws[CCH * 27 * NO];
    const int o0 = blockIdx.y * NO;
    const int b  = blockIdx.z;
    const int s  = blockIdx.x * 1024 + threadIdx.x * 4;   // voxels s..s+3
    const int z = s >> 10, y = (s >> 5) & 31, x0 = s & 31;
    const float* ib = bufsel(in_id, nullptr) + (size_t)b * CC * SS;

    ull acc[4][NO / 2];
    #pragma unroll
    for (int v = 0; v < 4; v++)
        #pragma unroll
        for (int q = 0; q < NO / 2; q++) acc[v][q] = 0ull;

    for (int cbase = 0; cbase < CC; cbase += CCH) {
        __syncthreads();
        for (int gidx = threadIdx.x; gidx < NO * CCH * 27; gidx += blockDim.x) {
            int oL  = gidx / (CCH * 27);
            int r   = gidx - oL * (CCH * 27);
            int cL  = r / 27;
            int tap = r - cL * 27;
            int og  = o0 + oL;
            ws[(cL * 27 + tap) * NO + oL] = (og < O)
                ? w[(size_t)og * (CC * 27) + (cbase + cL) * 27 + tap] : 0.f;
        }
        __syncthreads();

        for (int cL = 0; cL < CCH; cL++) {
            const float* ic = ib + (cbase + cL) * SS;
            const ulonglong2* wbase = (const ulonglong2*)(ws + cL * 27 * NO);
            #pragma unroll
            for (int kd = 0; kd < 3; kd++) {
                int zz = z + kd - 1; bool vz = (unsigned)zz < 32u;
                #pragma unroll
                for (int kh = 0; kh < 3; kh++) {
                    int yy = y + kh - 1; bool vy = (unsigned)yy < 32u;
                    int rbase = (zz << 10) + (yy << 5);
                    bool vzy = vz && vy;
                    // x-window r[0..5] = x0-1 .. x0+4
                    float r0 = (vzy && x0 >= 1) ? ic[rbase + x0 - 1] : 0.f;
                    float r1, r2, r3, r4;
                    if (vzy) {
                        float4 t = *(const float4*)(ic + rbase + x0);
                        r1 = t.x; r2 = t.y; r3 = t.z; r4 = t.w;
                    } else {
                        r1 = 0.f; r2 = 0.f; r3 = 0.f; r4 = 0.f;
                    }
                    float r5 = (vzy && x0 <= 27) ? ic[rbase + x0 + 4] : 0.f;
                    float rr[6] = {r0, r1, r2, r3, r4, r5};
                    int taprow = (kd * 3 + kh) * 3;
                    #pragma unroll
                    for (int kw = 0; kw < 3; kw++) {
                        ull vv0 = pack2(rr[kw + 0], rr[kw + 0]);
                        ull vv1 = pack2(rr[kw + 1], rr[kw + 1]);
                        ull vv2 = pack2(rr[kw + 2], rr[kw + 2]);
                        ull vv3 = pack2(rr[kw + 3], rr[kw + 3]);
                        const ulonglong2* wrow = wbase + (taprow + kw) * (NO / 4);
                        #pragma unroll
                        for (int q = 0; q < NO / 4; q++) {
                            ulonglong2 wq = wrow[q];
                            fma2(acc[0][2 * q + 0], wq.x, vv0);
                            fma2(acc[0][2 * q + 1], wq.y, vv0);
                            fma2(acc[1][2 * q + 0], wq.x, vv1);
                            fma2(acc[1][2 * q + 1], wq.y, vv1);
                            fma2(acc[2][2 * q + 0], wq.x, vv2);
                            fma2(acc[2][2 * q + 1], wq.y, vv2);
                            fma2(acc[3][2 * q + 0], wq.x, vv3);
                            fma2(acc[3][2 * q + 1], wq.y, vv3);
                        }
                    }
                }
            }
        }
    }

    // unpack: a[v][o]
    float a[4][NO];
    #pragma unroll
    for (int v = 0; v < 4; v++)
        #pragma unroll
        for (int q = 0; q < NO / 2; q++)
            unpack2(a[v][2 * q], a[v][2 * q + 1], acc[v][q]);

    float* outb = bufsel(out_id, nullptr) + (size_t)b * O * SS + s;
    if (mode == 0) {
        #pragma unroll
        for (int o = 0; o < NO; o++) {
            int og = o0 + o;
            if (og < O) {
                float bb = bias[og];
                *(float4*)&outb[og * SS] =
                    make_float4(a[0][o] + bb, a[1][o] + bb, a[2][o] + bb, a[3][o] + bb);
            }
        }
    } else {
        const float* skp = (mode == 2) ? bufsel(skip_id, nullptr) + (size_t)b * O * SS + s
                                       : nullptr;
        #pragma unroll
        for (int o = 0; o < NO; o++) {
            int og = o0 + o;
            float scale = bs2[og] * rsqrtf(bv[og] + 1e-5f);
            float sh = bbp[og] - bm[og] * scale;
            float h0 = a[0][o] * scale + sh;
            float h1 = a[1][o] * scale + sh;
            float h2 = a[2][o] * scale + sh;
            float h3 = a[3][o] * scale + sh;
            if (mode == 2) {
                float4 sv = *(const float4*)&skp[og * SS];
                h0 += sv.x; h1 += sv.y; h2 += sv.z; h3 += sv.w;
            }
            h0 = (h0 >= 0.f) ? h0 : 0.01f * h0;
            h1 = (h1 >= 0.f) ? h1 : 0.01f * h1;
            h2 = (h2 >= 0.f) ? h2 : 0.01f * h2;
            h3 = (h3 >= 0.f) ? h3 : 0.01f * h3;
            *(float4*)&outb[og * SS] = make_float4(h0, h1, h2, h3);
        }
    }
}

// ---------------- transpose dc_w [o][c][k] -> [k][c][o] ----------------
__global__ void k_wt(const float* __restrict__ w) {
    int i = blockIdx.x * blockDim.x + threadIdx.x;
    if (i >= CC * CC * 27) return;
    int o = i / (CC * 27);
    int r = i - o * (CC * 27);
    int c = r / 27;
    int k = r - c * 27;
    g_dcwt[(k * CC + c) * CC + o] = w[i];
}

// ---------------- deformable conv: 3-way tap split, 3-tap smem staging, f32x2 ----------------
__global__ void __launch_bounds__(256, 2) k_deform() {
    __shared__ __align__(16) float wt_s[3][CC * CC];
    int s = blockIdx.x * blockDim.x + threadIdx.x;
    int b = blockIdx.y;
    int g = blockIdx.z;
    int z = s >> 10, y = (s >> 5) & 31, x = s & 31;
    const float* a   = g_a2  + (size_t)b * CC * SS;
    const float* off = g_off + (size_t)b * OFFC * SS + s;

    ull acc2[CC / 2];
    #pragma unroll
    for (int q = 0; q < CC / 2; q++) acc2[q] = 0ull;

    #pragma unroll 1
    for (int kt0 = g * 9; kt0 < g * 9 + 9; kt0 += 3) {
        __syncthreads();
        {
            const float4* src = (const float4*)(g_dcwt + kt0 * CC * CC);
            float4* dst = (float4*)wt_s[0];
            for (int i = threadIdx.x; i < 3 * CC * CC / 4; i += blockDim.x)
                dst[i] = src[i];
        }
        __syncthreads();

        #pragma unroll 1
        for (int tloc = 0; tloc < 3; tloc++) {
            int kt = kt0 + tloc;
            int kd = kt / 9 - 1, kh = (kt / 3) % 3 - 1, kw = kt % 3 - 1;
            float zf = (float)(z + kd) + off[(kt * 3 + 0) * SS];
            float yf = (float)(y + kh) + off[(kt * 3 + 1) * SS];
            float xf = (float)(x + kw) + off[(kt * 3 + 2) * SS];
            float z0 = floorf(zf), y0 = floorf(yf), x0 = floorf(xf);
            float tz = zf - z0, ty = yf - y0, tx = xf - x0;
            int iz0 = (int)z0, iy0 = (int)y0, ix0 = (int)x0;

            int idx8[8];
            ull w8v[8];
            #pragma unroll
            for (int dz = 0; dz < 2; dz++)
            #pragma unroll
            for (int dy = 0; dy < 2; dy++)
            #pragma unroll
            for (int dx = 0; dx < 2; dx++) {
                int j = dz * 4 + dy * 2 + dx;
                int zi = iz0 + dz, yi = iy0 + dy, xi = ix0 + dx;
                bool valid = (zi >= 0 && zi < 32 && yi >= 0 && yi < 32 && xi >= 0 && xi < 32);
                float wg = (dz ? tz : 1.f - tz) * (dy ? ty : 1.f - ty) * (dx ? tx : 1.f - tx);
                int zc = min(max(zi, 0), 31), yc = min(max(yi, 0), 31), xc = min(max(xi, 0), 31);
                idx8[j] = (zc << 10) + (yc << 5) + xc;
                float wf = valid ? wg : 0.f;
                w8v[j] = pack2(wf, wf);
            }

            const float* wts = wt_s[tloc];
            for (int c = 0; c < CC; c += 2) {
                const float* ac0 = a + c * SS;
                const float* ac1 = ac0 + SS;
                ull valv = 0ull;
                #pragma unroll
                for (int j = 0; j < 8; j++)
                    fma2(valv, pack2(ac0[idx8[j]], ac1[idx8[j]]), w8v[j]);
                float v0, v1;
                unpack2(v0, v1, valv);
                ull vv0 = pack2(v0, v0), vv1 = pack2(v1, v1);

                const ulonglong2* w0 = (const ulonglong2*)(wts + (c + 0) * CC);
                const ulonglong2* w1 = (const ulonglong2*)(wts + (c + 1) * CC);
                #pragma unroll
                for (int q = 0; q < CC / 4; q++) {
                    ulonglong2 wa = w0[q];
                    fma2(acc2[2 * q + 0], wa.x, vv0);
                    fma2(acc2[2 * q + 1], wa.y, vv0);
                }
                #pragma unroll
                for (int q = 0; q < CC / 4; q++) {
                    ulonglong2 wb = w1[q];
                    fma2(acc2[2 * q + 0], wb.x, vv1);
                    fma2(acc2[2 * q + 1], wb.y, vv1);
                }
            }
        }
    }

    int outid = (g == 0) ? 5 : (g == 1) ? 7 : 8;
    float* ob = bufsel(outid, nullptr) + (size_t)b * CC * SS + s;
    #pragma unroll
    for (int q = 0; q < CC / 2; q++) {
        float a0, a1;
        unpack2(a0, a1, acc2[q]);
        ob[(2 * q + 0) * SS] = a0;
        ob[(2 * q + 1) * SS] = a1;
    }
}

// ---------------- launch: kernel launches ONLY ----------------
extern "C" void kernel_launch(void* const* d_in, const int* in_sizes, int n_in,
                              void* d_out, int out_size) {
    const float* x     = (const float*)d_in[0];
    const float* ln_s  = (const float*)d_in[1];
    const float* ln_b  = (const float*)d_in[2];
    const float* gamma = (const float*)d_in[3];
    const float* p1_w  = (const float*)d_in[4];
    const float* p1_b  = (const float*)d_in[5];
    const float* p2_w  = (const float*)d_in[6];
    const float* p2_b  = (const float*)d_in[7];
    const float* c0_w  = (const float*)d_in[8];
    const float* c0_b  = (const float*)d_in[9];
    const float* cs_w  = (const float*)d_in[10];
    const float* cs_b  = (const float*)d_in[11];
    const float* off_w = (const float*)d_in[12];
    const float* off_b = (const float*)d_in[13];
    const float* dc_w  = (const float*)d_in[14];
    const float* dc_b  = (const float*)d_in[15];
    const float* c1_w  = (const float*)d_in[16];
    const float* c1_b  = (const float*)d_in[17];
    const float* u1_w  = (const float*)d_in[18];
    const float* bn1_s = (const float*)d_in[19];
    const float* bn1_b = (const float*)d_in[20];
    const float* bn1_m = (const float*)d_in[21];
    const float* bn1_v = (const float*)d_in[22];
    const float* u2_w  = (const float*)d_in[23];
    const float* bn2_s = (const float*)d_in[24];
    const float* bn2_b = (const float*)d_in[25];
    const float* bn2_m = (const float*)d_in[26];
    const float* bn2_v = (const float*)d_in[27];
    const float* pr_w  = (const float*)d_in[28];
    const float* pr_b  = (const float*)d_in[29];
    float* out = (float*)d_out;

    dim3 pwGrid((BB * SS) / 256);
    dim3 dwGrid(SS / 1024, CC, BB);
    dim3 c3OffGrid(SS / 1024, 7, BB);   // 4 voxels/thread, 7 chunks of 12 (84 >= 81)
    dim3 c3UGrid(SS / 1024, 4, BB);     // 4 voxels/thread, 4 chunks of 12

    // 1. fused LayerNorm + proj_1 + GELU: x -> g_xn (0), g_u (1)
    k_lnpw<<<pwGrid, 256>>>(x, ln_s, ln_b, p1_w, p1_b);
    // 2. depthwise 5x5x5 pad 2: g_u -> g_a1 (2)
    k_dw<5, 2, 1><<<dwGrid, 256>>>(1, c0_w, c0_b, 2);
    // 3. depthwise 7x7x7 dil 3 pad 9: g_a1 -> g_a2 (3)
    k_dw<7, 9, 3><<<dwGrid, 256>>>(2, cs_w, cs_b, 3);
    // 4. offset conv 3x3x3 -> 81 channels: g_a2 -> g_off (4)
    k_c3g<12, 8><<<c3OffGrid, 256>>>(3, off_w, off_b,
                                     nullptr, nullptr, nullptr, nullptr,
                                     -1, 4, OFFC, 0);
    // 5. transpose deform weights
    k_wt<<<(CC * CC * 27 + 255) / 256, 256>>>(dc_w);
    // 6. deformable conv, 3 tap groups: partials -> g_a3 (5), g_h1 (7), g_attn (8)
    k_deform<<<dim3(SS / 256, BB, 3), 256>>>();
    // 7+8 fused: c1 GEMM + gate + p2 GEMM + residuals -> g_skip (6)
    k_pwgate<<<pwGrid, 256>>>(c1_w, c1_b, dc_b, p2_w, p2_b, x, gamma);
    // 9. u1 conv3 + BN1 + leaky: g_skip -> g_h1 (7)
    k_c3g<12, 8><<<c3UGrid, 256>>>(6, u1_w, nullptr,
                                   bn1_s, bn1_b, bn1_m, bn1_v,
                                   -1, 7, CC, 1);
    // 10. u2 conv3 + BN2 + skip + leaky: g_h1 -> g_attn (8)
    k_c3g<12, 8><<<c3UGrid, 256>>>(7, u2_w, nullptr,
                                   bn2_s, bn2_b, bn2_m, bn2_v,
                                   6, 8, CC, 2);
    // 11. projconv 1x1x1 + skip -> out (external)
    k_pw48<<<pwGrid, 256>>>(8, pr_w, pr_b, 6, out);
}